// round 10
// baseline (speedup 1.0000x reference)
#include <cuda_runtime.h>
#include <cstdint>
#include <cstddef>

// Problem dims (fixed by the reference)
#define Bt 1024
#define Tt 512
#define Ii 45
#define Hh 128
#define Oo 45

#define NBMAX 4          // max batch rows per CTA (balanced 3-4)
#define NTH 256          // jp = tid&63 -> j{2jp,2jp+1}; qt = tid>>6 -> k quarter
#define NBLK 294         // 2 CTAs per SM, single wave

typedef unsigned long long ull;

// 256 MB scratch for the precomputed input contribution:
// xe[bt][j] = b_ih[j] + b_hh[j] + sum_i x[bt][i] * W_ih[j][i]
__device__ float xe_buf[(size_t)Bt * Tt * Hh];

__device__ __forceinline__ void fma2(ull& acc, ull a, ull b) {
    asm("fma.rn.f32x2 %0, %1, %2, %0;" : "+l"(acc) : "l"(a), "l"(b));
}
__device__ __forceinline__ void add2(ull& acc, ull a) {
    asm("add.rn.f32x2 %0, %0, %1;" : "+l"(acc) : "l"(a));
}
__device__ __forceinline__ float2 unpack2(ull d) {
    unsigned lo, hi;
    asm("mov.b64 {%0, %1}, %2;" : "=r"(lo), "=r"(hi) : "l"(d));
    return make_float2(__uint_as_float(lo), __uint_as_float(hi));
}
__device__ __forceinline__ ull pack2f(float lo, float hi) {
    ull d;
    asm("mov.b64 %0, {%1, %2};" : "=l"(d)
        : "r"(__float_as_uint(lo)), "r"(__float_as_uint(hi)));
    return d;
}

// tanh(x) = 1 - 2/(exp(2x)+1): ~1e-6 abs err, exact +/-1 saturation.
__device__ __forceinline__ float fast_tanh(float x) {
    float e = __expf(2.0f * x);
    return 1.0f - __fdividef(2.0f, e + 1.0f);
}

// ============================================================================
// Pre-pass: xe = x @ W_ih^T + b_ih + b_hh   (no sequential dependence)
// Grid 4096 CTAs x 256 thr; CTA tile = 128 bt rows x all 128 j.
// Thread = (jp in [0,64), btg in [0,4)): j pair {2jp,2jp+1}, 32 bt rows.
// ============================================================================
__global__ void __launch_bounds__(NTH, 2)
xe_prepass_kernel(const float* __restrict__ x,
                  const float* __restrict__ W_ih,
                  const float* __restrict__ b_ih,
                  const float* __restrict__ b_hh)
{
    __shared__ float xs[128 * 48];   // [bt_local][i48], i 45..47 zero-padded

    const int tid = threadIdx.x;
    const int jp  = tid & 63, btg = tid >> 6;
    const int j0  = 2 * jp, j1 = j0 + 1;
    const size_t btBase = (size_t)blockIdx.x * 128;

    // Stage x tile (coalesced enough; 45 of 48 columns real)
    for (int idx = tid; idx < 128 * 48; idx += NTH) {
        const int btl = idx / 48, ii = idx - btl * 48;
        xs[idx] = (ii < Ii) ? x[(btBase + btl) * Ii + ii] : 0.0f;
    }

    // Weight rows j0/j1 packed over i-pairs (24 pairs incl. zero pad)
    ull wA[12 * 2], wB[12 * 2];
    #pragma unroll
    for (int p = 0; p < 24; ++p) {
        const int ia = 2 * p, ib = 2 * p + 1;
        const float a0 = (ia < Ii) ? W_ih[j0 * Ii + ia] : 0.0f;
        const float a1 = (ib < Ii) ? W_ih[j0 * Ii + ib] : 0.0f;
        const float c0 = (ia < Ii) ? W_ih[j1 * Ii + ia] : 0.0f;
        const float c1 = (ib < Ii) ? W_ih[j1 * Ii + ib] : 0.0f;
        wA[p] = pack2f(a0, a1);
        wB[p] = pack2f(c0, c1);
    }
    const float bi0 = b_ih[j0] + b_hh[j0];
    const float bi1 = b_ih[j1] + b_hh[j1];
    __syncthreads();

    // 8 chunks of 4 bt rows each (thread covers bt [32*btg, 32*btg+32))
    for (int c = 0; c < 8; ++c) {
        const int bt0 = btg * 32 + c * 4;
        ull aA[4] = {0ull, 0ull, 0ull, 0ull};
        ull aB[4] = {0ull, 0ull, 0ull, 0ull};

        #pragma unroll
        for (int q = 0; q < 12; ++q) {           // i-quads; LDS.128 broadcast
            #pragma unroll
            for (int r = 0; r < 4; ++r) {
                const ulonglong2 v = *reinterpret_cast<const ulonglong2*>(
                    xs + (bt0 + r) * 48 + q * 4);
                fma2(aA[r], wA[2 * q], v.x); fma2(aA[r], wA[2 * q + 1], v.y);
                fma2(aB[r], wB[2 * q], v.x); fma2(aB[r], wB[2 * q + 1], v.y);
            }
        }

        #pragma unroll
        for (int r = 0; r < 4; ++r) {
            const float2 fA = unpack2(aA[r]);
            const float2 fB = unpack2(aB[r]);
            float2 o;
            o.x = bi0 + fA.x + fA.y;
            o.y = bi1 + fB.x + fB.y;
            *reinterpret_cast<float2*>(
                xe_buf + (btBase + bt0 + r) * Hh + j0) = o;
        }
    }
}

// ============================================================================
// Recurrence loop: h_{t+1} = tanh(xe_t + h_t @ W_hh^T), then final FC.
// ============================================================================
__global__ void __launch_bounds__(NTH, 2)
rnn_loop_kernel(const float* __restrict__ W_hh,
                const float* __restrict__ W_fc,
                const float* __restrict__ b_fc,
                float* __restrict__ out)
{
    __shared__ float sm[2 * NBMAX * Hh + 4 * NBMAX * Hh * 2];  // 20 KB
    float* hT  = sm;                                            // [2][4][128]
    ull*  part = reinterpret_cast<ull*>(sm + 2 * NBMAX * Hh);   // [4][4][128]

    const int tid = threadIdx.x;
    const int jp  = tid & 63;       // j pair: j0 = 2jp, j1 = 2jp+1
    const int qt  = tid >> 6;       // k quarter [32qt, 32qt+32)
    const int j0  = 2 * jp, j1 = 2 * jp + 1;

    const int bid = blockIdx.x;
    const int rowStart = (bid * Bt) / NBLK;
    const int rowEnd   = ((bid + 1) * Bt) / NBLK;
    const int nb = rowEnd - rowStart;           // 3 or 4

    for (int idx = tid; idx < 2 * NBMAX * Hh; idx += NTH) hT[idx] = 0.0f;

    // W_hh rows j0/j1, k slice, straight from GMEM (L2-broadcast, one-time)
    ull wkA[16], wkB[16];
    {
        const float* wa = W_hh + j0 * Hh + qt * 32;
        const float* wb = W_hh + j1 * Hh + qt * 32;
        #pragma unroll
        for (int q = 0; q < 16; ++q) {
            wkA[q] = *reinterpret_cast<const ull*>(wa + 2 * q);
            wkB[q] = *reinterpret_cast<const ull*>(wb + 2 * q);
        }
    }

    // This thread finishes row qt; its xe stream (clamped for pad rows)
    const int myRow = (rowStart + qt < Bt) ? (rowStart + qt) : (Bt - 1);
    const float* xe_p = xe_buf + ((size_t)myRow * Tt) * Hh + j0;
    float2 xe_cur = *reinterpret_cast<const float2*>(xe_p);   // t = 0

    __syncthreads();

    for (int t = 0; t < Tt; ++t) {
        const int cur = t & 1;
        const float* hc = hT + cur * (NBMAX * Hh) + qt * 32;

        // Prefetch next step's xe (hidden behind the FMA loop)
        float2 xe_nxt = make_float2(0.0f, 0.0f);
        if (t + 1 < Tt)
            xe_nxt = *reinterpret_cast<const float2*>(xe_p + (size_t)(t + 1) * Hh);

        // Packed accumulators per (j, row): lanes = (even-k, odd-k) partials
        ull aA[NBMAX], aB[NBMAX];
        #pragma unroll
        for (int r = 0; r < NBMAX; ++r) { aA[r] = 0ull; aB[r] = 0ull; }

        // Recurrent contribution: 8 k-quads; each broadcast LDS.128 feeds 4 fma2
        #pragma unroll
        for (int q = 0; q < 8; ++q) {
            const ull wA0 = wkA[2 * q], wA1 = wkA[2 * q + 1];
            const ull wB0 = wkB[2 * q], wB1 = wkB[2 * q + 1];
            #pragma unroll
            for (int r = 0; r < NBMAX; ++r) {
                const ulonglong2 v =
                    *reinterpret_cast<const ulonglong2*>(hc + r * Hh + q * 4);
                fma2(aA[r], wA0, v.x); fma2(aA[r], wA1, v.y);
                fma2(aB[r], wB0, v.x); fma2(aB[r], wB1, v.y);
            }
        }

        // Post partials (16B STS) for the 3 rows this quarter does not finish
        ull* myp = part + (qt * NBMAX) * Hh + j0;
        #pragma unroll
        for (int r = 0; r < NBMAX; ++r) {
            if (r != qt) {
                ulonglong2 v; v.x = aA[r]; v.y = aB[r];
                *reinterpret_cast<ulonglong2*>(myp + r * Hh) = v;
            }
        }
        __syncthreads();

        // Finish row r == qt: sum quarters, add xe (bias included), tanh
        {
            const int r = qt;
            ull sA = aA[r], sB = aB[r];
            #pragma unroll
            for (int qq = 0; qq < 4; ++qq) {
                if (qq != qt) {
                    const ulonglong2 p = *reinterpret_cast<const ulonglong2*>(
                        part + (qq * NBMAX + r) * Hh + j0);
                    add2(sA, p.x);
                    add2(sB, p.y);
                }
            }
            const float2 fA = unpack2(sA);
            const float2 fB = unpack2(sB);
            float2 o;
            o.x = fast_tanh(fA.x + fA.y + xe_cur.x);
            o.y = fast_tanh(fB.x + fB.y + xe_cur.y);
            float* hn = hT + (cur ^ 1) * (NBMAX * Hh);
            *reinterpret_cast<float2*>(hn + r * Hh + j0) = o;
        }
        xe_cur = xe_nxt;

        __syncthreads();
    }

    // ---- Final FC: out[b][o] = b_fc[o] + sum_j W_fc[o][j] * h_last[b][j] ----
    // Tt even -> last h landed in buffer 0. Layout [row][j], contiguous in j.
    const float* hlast = hT;
    if (tid < nb * Oo) {
        const int b = tid / Oo;
        const int o = tid - b * Oo;
        float s = b_fc[o];
        const float* wp = W_fc + o * Hh;
        const float* hp = hlast + b * Hh;
        #pragma unroll 8
        for (int jj = 0; jj < Hh; ++jj)
            s = fmaf(wp[jj], hp[jj], s);
        out[(rowStart + b) * Oo + o] = s;
    }
}

extern "C" void kernel_launch(void* const* d_in, const int* in_sizes, int n_in,
                              void* d_out, int out_size)
{
    const float* x   = (const float*)d_in[0];
    const float* Wih = (const float*)d_in[1];
    const float* bih = (const float*)d_in[2];
    const float* Whh = (const float*)d_in[3];
    const float* bhh = (const float*)d_in[4];
    const float* Wfc = (const float*)d_in[5];
    const float* bfc = (const float*)d_in[6];
    float* out = (float*)d_out;

    // Pre-pass: 524288 bt rows / 128 per CTA = 4096 CTAs
    xe_prepass_kernel<<<4096, NTH>>>(x, Wih, bih, bhh);
    // Sequential recurrence + final FC
    rnn_loop_kernel<<<NBLK, NTH>>>(Whh, Wfc, bfc, out);
}

// round 11
// speedup vs baseline: 1.0533x; 1.0533x over previous
#include <cuda_runtime.h>
#include <cstdint>
#include <cstddef>

// Problem dims (fixed by the reference)
#define Bt 1024
#define Tt 512
#define Ii 45
#define Hh 128
#define Oo 45

#define NBMAX 4          // max batch rows per CTA (balanced 3-4)
#define NTH 256          // jp = tid&63 -> j{2jp,2jp+1}; qt = tid>>6 -> k quarter
#define NBLK 294         // 2 CTAs per SM, single wave

typedef unsigned long long ull;

// 256 MB scratch for the precomputed input contribution:
// xe[bt][j] = b_ih[j] + b_hh[j] + sum_i x[bt][i] * W_ih[j][i]
__device__ float xe_buf[(size_t)Bt * Tt * Hh];

__device__ __forceinline__ void fma2(ull& acc, ull a, ull b) {
    asm("fma.rn.f32x2 %0, %1, %2, %0;" : "+l"(acc) : "l"(a), "l"(b));
}
__device__ __forceinline__ void add2(ull& acc, ull a) {
    asm("add.rn.f32x2 %0, %0, %1;" : "+l"(acc) : "l"(a));
}
__device__ __forceinline__ float2 unpack2(ull d) {
    unsigned lo, hi;
    asm("mov.b64 {%0, %1}, %2;" : "=r"(lo), "=r"(hi) : "l"(d));
    return make_float2(__uint_as_float(lo), __uint_as_float(hi));
}
__device__ __forceinline__ ull pack2f(float lo, float hi) {
    ull d;
    asm("mov.b64 %0, {%1, %2};" : "=l"(d)
        : "r"(__float_as_uint(lo)), "r"(__float_as_uint(hi)));
    return d;
}

// tanh(x) = 1 - 2/(exp(2x)+1): ~1e-6 abs err, exact +/-1 saturation.
__device__ __forceinline__ float fast_tanh(float x) {
    float e = __expf(2.0f * x);
    return 1.0f - __fdividef(2.0f, e + 1.0f);
}

// ============================================================================
// Pre-pass: xe = x @ W_ih^T + b_ih + b_hh   (no sequential dependence)
// Grid 4096 CTAs x 256 thr; CTA tile = 128 bt rows x all 128 j.
// v2: W_ih staged into SMEM as packed ull pairs (kills the GMEM scatter that
//     dominated R10's prepass), then copied to registers once per thread.
// ============================================================================
__global__ void __launch_bounds__(NTH, 2)
xe_prepass_kernel(const float* __restrict__ x,
                  const float* __restrict__ W_ih,
                  const float* __restrict__ b_ih,
                  const float* __restrict__ b_hh)
{
    __shared__ float xs[128 * 48];   // [bt_local][i48], i 45..47 zero (24576 B)
    __shared__ ull   wp2[24 * 128];  // [i_pair][j] packed pairs     (24576 B)

    const int tid = threadIdx.x;
    const int jp  = tid & 63, btg = tid >> 6;
    const int j0  = 2 * jp, j1 = j0 + 1;
    const size_t btBase = (size_t)blockIdx.x * 128;

    // Stage x tile
    for (int idx = tid; idx < 128 * 48; idx += NTH) {
        const int btl = idx / 48, ii = idx - btl * 48;
        xs[idx] = (ii < Ii) ? x[(btBase + btl) * Ii + ii] : 0.0f;
    }

    // Stage W_ih as packed pairs: wp2[p][j] = (W[j][2p], W[j][2p+1]), zero pad.
    // idx = j*24 + p -> gmem reads are consecutive 8B within a row (coalesced).
    for (int idx = tid; idx < 128 * 24; idx += NTH) {
        const int jj = idx / 24, p = idx - jj * 24;
        const int ia = 2 * p, ib = ia + 1;
        const float w0 = (ia < Ii) ? W_ih[jj * Ii + ia] : 0.0f;
        const float w1 = (ib < Ii) ? W_ih[jj * Ii + ib] : 0.0f;
        wp2[p * 128 + jj] = pack2f(w0, w1);
    }
    const float bi0 = b_ih[j0] + b_hh[j0];
    const float bi1 = b_ih[j1] + b_hh[j1];
    __syncthreads();

    // Pull this thread's weight pairs from SMEM into registers (one-time)
    ull wA[24], wB[24];
    #pragma unroll
    for (int p = 0; p < 24; ++p) {
        wA[p] = wp2[p * 128 + j0];
        wB[p] = wp2[p * 128 + j1];
    }

    // 8 chunks of 4 bt rows each (thread covers bt [32*btg, 32*btg+32))
    for (int c = 0; c < 8; ++c) {
        const int bt0 = btg * 32 + c * 4;
        ull aA[4] = {0ull, 0ull, 0ull, 0ull};
        ull aB[4] = {0ull, 0ull, 0ull, 0ull};

        #pragma unroll
        for (int q = 0; q < 12; ++q) {           // i-quads; LDS.128 broadcast
            #pragma unroll
            for (int r = 0; r < 4; ++r) {
                const ulonglong2 v = *reinterpret_cast<const ulonglong2*>(
                    xs + (bt0 + r) * 48 + q * 4);
                fma2(aA[r], wA[2 * q], v.x); fma2(aA[r], wA[2 * q + 1], v.y);
                fma2(aB[r], wB[2 * q], v.x); fma2(aB[r], wB[2 * q + 1], v.y);
            }
        }

        #pragma unroll
        for (int r = 0; r < 4; ++r) {
            const float2 fA = unpack2(aA[r]);
            const float2 fB = unpack2(aB[r]);
            float2 o;
            o.x = bi0 + fA.x + fA.y;
            o.y = bi1 + fB.x + fB.y;
            *reinterpret_cast<float2*>(
                xe_buf + (btBase + bt0 + r) * Hh + j0) = o;
        }
    }
}

// ============================================================================
// Recurrence loop: h_{t+1} = tanh(xe_t + h_t @ W_hh^T), then final FC.
// (unchanged from R10 — measured 705 us)
// ============================================================================
__global__ void __launch_bounds__(NTH, 2)
rnn_loop_kernel(const float* __restrict__ W_hh,
                const float* __restrict__ W_fc,
                const float* __restrict__ b_fc,
                float* __restrict__ out)
{
    __shared__ float sm[2 * NBMAX * Hh + 4 * NBMAX * Hh * 2];  // 20 KB
    float* hT  = sm;                                            // [2][4][128]
    ull*  part = reinterpret_cast<ull*>(sm + 2 * NBMAX * Hh);   // [4][4][128]

    const int tid = threadIdx.x;
    const int jp  = tid & 63;       // j pair: j0 = 2jp, j1 = 2jp+1
    const int qt  = tid >> 6;       // k quarter [32qt, 32qt+32)
    const int j0  = 2 * jp, j1 = 2 * jp + 1;

    const int bid = blockIdx.x;
    const int rowStart = (bid * Bt) / NBLK;
    const int rowEnd   = ((bid + 1) * Bt) / NBLK;
    const int nb = rowEnd - rowStart;           // 3 or 4

    for (int idx = tid; idx < 2 * NBMAX * Hh; idx += NTH) hT[idx] = 0.0f;

    // W_hh rows j0/j1, k slice, straight from GMEM (L2-broadcast, one-time)
    ull wkA[16], wkB[16];
    {
        const float* wa = W_hh + j0 * Hh + qt * 32;
        const float* wb = W_hh + j1 * Hh + qt * 32;
        #pragma unroll
        for (int q = 0; q < 16; ++q) {
            wkA[q] = *reinterpret_cast<const ull*>(wa + 2 * q);
            wkB[q] = *reinterpret_cast<const ull*>(wb + 2 * q);
        }
    }

    // This thread finishes row qt; its xe stream (clamped for pad rows)
    const int myRow = (rowStart + qt < Bt) ? (rowStart + qt) : (Bt - 1);
    const float* xe_p = xe_buf + ((size_t)myRow * Tt) * Hh + j0;
    float2 xe_cur = *reinterpret_cast<const float2*>(xe_p);   // t = 0

    __syncthreads();

    for (int t = 0; t < Tt; ++t) {
        const int cur = t & 1;
        const float* hc = hT + cur * (NBMAX * Hh) + qt * 32;

        // Prefetch next step's xe (hidden behind the FMA loop)
        float2 xe_nxt = make_float2(0.0f, 0.0f);
        if (t + 1 < Tt)
            xe_nxt = *reinterpret_cast<const float2*>(xe_p + (size_t)(t + 1) * Hh);

        // Packed accumulators per (j, row): lanes = (even-k, odd-k) partials
        ull aA[NBMAX], aB[NBMAX];
        #pragma unroll
        for (int r = 0; r < NBMAX; ++r) { aA[r] = 0ull; aB[r] = 0ull; }

        // Recurrent contribution: 8 k-quads; each broadcast LDS.128 feeds 4 fma2
        #pragma unroll
        for (int q = 0; q < 8; ++q) {
            const ull wA0 = wkA[2 * q], wA1 = wkA[2 * q + 1];
            const ull wB0 = wkB[2 * q], wB1 = wkB[2 * q + 1];
            #pragma unroll
            for (int r = 0; r < NBMAX; ++r) {
                const ulonglong2 v =
                    *reinterpret_cast<const ulonglong2*>(hc + r * Hh + q * 4);
                fma2(aA[r], wA0, v.x); fma2(aA[r], wA1, v.y);
                fma2(aB[r], wB0, v.x); fma2(aB[r], wB1, v.y);
            }
        }

        // Post partials (16B STS) for the 3 rows this quarter does not finish
        ull* myp = part + (qt * NBMAX) * Hh + j0;
        #pragma unroll
        for (int r = 0; r < NBMAX; ++r) {
            if (r != qt) {
                ulonglong2 v; v.x = aA[r]; v.y = aB[r];
                *reinterpret_cast<ulonglong2*>(myp + r * Hh) = v;
            }
        }
        __syncthreads();

        // Finish row r == qt: sum quarters, add xe (bias included), tanh
        {
            const int r = qt;
            ull sA = aA[r], sB = aB[r];
            #pragma unroll
            for (int qq = 0; qq < 4; ++qq) {
                if (qq != qt) {
                    const ulonglong2 p = *reinterpret_cast<const ulonglong2*>(
                        part + (qq * NBMAX + r) * Hh + j0);
                    add2(sA, p.x);
                    add2(sB, p.y);
                }
            }
            const float2 fA = unpack2(sA);
            const float2 fB = unpack2(sB);
            float2 o;
            o.x = fast_tanh(fA.x + fA.y + xe_cur.x);
            o.y = fast_tanh(fB.x + fB.y + xe_cur.y);
            float* hn = hT + (cur ^ 1) * (NBMAX * Hh);
            *reinterpret_cast<float2*>(hn + r * Hh + j0) = o;
        }
        xe_cur = xe_nxt;

        __syncthreads();
    }

    // ---- Final FC: out[b][o] = b_fc[o] + sum_j W_fc[o][j] * h_last[b][j] ----
    // Tt even -> last h landed in buffer 0. Layout [row][j], contiguous in j.
    const float* hlast = hT;
    if (tid < nb * Oo) {
        const int b = tid / Oo;
        const int o = tid - b * Oo;
        float s = b_fc[o];
        const float* wp = W_fc + o * Hh;
        const float* hp = hlast + b * Hh;
        #pragma unroll 8
        for (int jj = 0; jj < Hh; ++jj)
            s = fmaf(wp[jj], hp[jj], s);
        out[(rowStart + b) * Oo + o] = s;
    }
}

extern "C" void kernel_launch(void* const* d_in, const int* in_sizes, int n_in,
                              void* d_out, int out_size)
{
    const float* x   = (const float*)d_in[0];
    const float* Wih = (const float*)d_in[1];
    const float* bih = (const float*)d_in[2];
    const float* Whh = (const float*)d_in[3];
    const float* bhh = (const float*)d_in[4];
    const float* Wfc = (const float*)d_in[5];
    const float* bfc = (const float*)d_in[6];
    float* out = (float*)d_out;

    // Pre-pass: 524288 bt rows / 128 per CTA = 4096 CTAs
    xe_prepass_kernel<<<4096, NTH>>>(x, Wih, bih, bhh);
    // Sequential recurrence + final FC
    rnn_loop_kernel<<<NBLK, NTH>>>(Whh, Wfc, bfc, out);
}